// round 6
// baseline (speedup 1.0000x reference)
#include <cuda_runtime.h>
#include <math.h>

#define NB 32
#define LL 1024
#define NI 600
#define NH 200
#define NR (NB*LL)

// ---------------- scratch (device globals; no runtime allocation) ----------
__device__ float g_t [NR*NH];                 // MLP layer1 temp
__device__ float g_h1[NR*NH];                 // mlp(s1)
__device__ float g_h2[NR*NH];                 // mlp(s2)
__device__ float g_e [(size_t)NB*LL*LL];      // e, then in-place exp for beta
__device__ float g_ea[(size_t)NB*LL*LL];      // un-normalized exp for alpha
__device__ float g_ia[NR];                    // 1/sum per (b,m) for alpha
__device__ float g_ib[NR];                    // 1/sum per (b,l) for beta

// ---------------------------------------------------------------------------
// GEMM 1: C[M,N] = relu(A[M,K] @ W[K,N] + bias[N])   (row-major, NN)
// tiles 64x64x16, 256 threads, 4x4 per thread
// ---------------------------------------------------------------------------
__global__ __launch_bounds__(256)
void k_gemm_bias_relu(const float* __restrict__ A,
                      const float* __restrict__ W,
                      const float* __restrict__ bias,
                      float* __restrict__ C,
                      int M, int N, int K) {
    __shared__ __align__(16) float As[16][64];
    __shared__ __align__(16) float Bs[16][64];
    int tid = threadIdx.x;
    int tx = tid & 15, ty = tid >> 4;
    int row0 = blockIdx.y * 64, col0 = blockIdx.x * 64;
    float acc[4][4] = {};
    for (int k0 = 0; k0 < K; k0 += 16) {
        #pragma unroll
        for (int t = 0; t < 4; t++) {
            int idx = tid + t*256;
            int r = idx >> 4, kk = idx & 15;
            int gr = row0 + r, gk = k0 + kk;
            As[kk][r] = (gr < M && gk < K) ? A[(size_t)gr*K + gk] : 0.f;
        }
        #pragma unroll
        for (int t = 0; t < 4; t++) {
            int idx = tid + t*256;
            int c = idx & 63, kk = idx >> 6;
            int gk = k0 + kk, gc = col0 + c;
            Bs[kk][c] = (gk < K && gc < N) ? W[(size_t)gk*N + gc] : 0.f;
        }
        __syncthreads();
        #pragma unroll
        for (int kk = 0; kk < 16; kk++) {
            float4 a4 = *reinterpret_cast<const float4*>(&As[kk][ty*4]);
            float4 b4 = *reinterpret_cast<const float4*>(&Bs[kk][tx*4]);
            float a[4] = {a4.x, a4.y, a4.z, a4.w};
            float b[4] = {b4.x, b4.y, b4.z, b4.w};
            #pragma unroll
            for (int i = 0; i < 4; i++)
                #pragma unroll
                for (int j = 0; j < 4; j++)
                    acc[i][j] = fmaf(a[i], b[j], acc[i][j]);
        }
        __syncthreads();
    }
    #pragma unroll
    for (int i = 0; i < 4; i++) {
        int r = row0 + ty*4 + i;
        if (r >= M) continue;
        #pragma unroll
        for (int j = 0; j < 4; j++) {
            int c = col0 + tx*4 + j;
            if (c < N) C[(size_t)r*N + c] = fmaxf(acc[i][j] + bias[c], 0.f);
        }
    }
}

// ---------------------------------------------------------------------------
// GEMM 2 (batched NT): e[b,l,m] = sum_d h1[b,l,d] * h2[b,m,d]   K=200
// M=N=1024 (multiples of 64 -> no row/col guards)
// ---------------------------------------------------------------------------
__global__ __launch_bounds__(256)
void k_gemm_e() {
    int b = blockIdx.z;
    const float* A  = g_h1 + (size_t)b*LL*NH;
    const float* Bm = g_h2 + (size_t)b*LL*NH;
    float*       C  = g_e  + (size_t)b*LL*LL;
    __shared__ __align__(16) float As[16][64];
    __shared__ __align__(16) float Bs[16][64];
    int tid = threadIdx.x;
    int tx = tid & 15, ty = tid >> 4;
    int row0 = blockIdx.y * 64, col0 = blockIdx.x * 64;
    float acc[4][4] = {};
    for (int k0 = 0; k0 < NH; k0 += 16) {
        #pragma unroll
        for (int t = 0; t < 4; t++) {
            int idx = tid + t*256;
            int r = idx >> 4, kk = idx & 15;
            int gk = k0 + kk;
            As[kk][r] = (gk < NH) ? A[(size_t)(row0 + r)*NH + gk] : 0.f;
        }
        #pragma unroll
        for (int t = 0; t < 4; t++) {
            int idx = tid + t*256;
            int r = idx >> 4, kk = idx & 15;
            int gk = k0 + kk;
            Bs[kk][r] = (gk < NH) ? Bm[(size_t)(col0 + r)*NH + gk] : 0.f;
        }
        __syncthreads();
        #pragma unroll
        for (int kk = 0; kk < 16; kk++) {
            float4 a4 = *reinterpret_cast<const float4*>(&As[kk][ty*4]);
            float4 b4 = *reinterpret_cast<const float4*>(&Bs[kk][tx*4]);
            float a[4] = {a4.x, a4.y, a4.z, a4.w};
            float bb[4] = {b4.x, b4.y, b4.z, b4.w};
            #pragma unroll
            for (int i = 0; i < 4; i++)
                #pragma unroll
                for (int j = 0; j < 4; j++)
                    acc[i][j] = fmaf(a[i], bb[j], acc[i][j]);
        }
        __syncthreads();
    }
    #pragma unroll
    for (int i = 0; i < 4; i++) {
        int r = row0 + ty*4 + i;
        #pragma unroll
        for (int j = 0; j < 4; j++) {
            int c = col0 + tx*4 + j;
            C[(size_t)r*LL + c] = acc[i][j];
        }
    }
}

// ---------------------------------------------------------------------------
// Alpha softmax (over l, per column m): writes UN-normalized exp into g_ea
// and 1/sum into g_ia.  logit[l,m] = e[l,m] * mask1[b,l]
// grid (LL/256, NB), block 256 : thread owns one column m
// ---------------------------------------------------------------------------
__global__ __launch_bounds__(256)
void k_softmax_cols(const float* __restrict__ mask1) {
    int b = blockIdx.y;
    int m = blockIdx.x * 256 + threadIdx.x;
    const float* pe = g_e  + (size_t)b*LL*LL + m;
    float*       po = g_ea + (size_t)b*LL*LL + m;
    __shared__ float smk[LL];
    for (int l = threadIdx.x; l < LL; l += 256) smk[l] = mask1[b*LL + l];
    __syncthreads();
    float mx = -3.4e38f;
    for (int l = 0; l < LL; l++) {
        float v = pe[(size_t)l*LL] * smk[l];
        mx = fmaxf(mx, v);
    }
    float s = 0.f;
    for (int l = 0; l < LL; l++) {
        float t = __expf(pe[(size_t)l*LL] * smk[l] - mx);
        po[(size_t)l*LL] = t;
        s += t;
    }
    g_ia[b*LL + m] = 1.f / s;
}

// ---------------------------------------------------------------------------
// Beta softmax (over m, per row l): IN-PLACE on g_e (un-normalized exp),
// 1/sum into g_ib.  logit[l,m] = e[l,m] * mask2[b,m]
// grid (NR), block 256 : block owns one row (4 elems / thread)
// ---------------------------------------------------------------------------
__global__ __launch_bounds__(256)
void k_softmax_rows(const float* __restrict__ mask2) {
    int row = blockIdx.x;        // b*LL + l
    int b = row >> 10;
    float* p = g_e + (size_t)row*LL;
    const float* mk = mask2 + b*LL;
    int tid = threadIdx.x;
    __shared__ float red[256];
    float v[4];
    float mx = -3.4e38f;
    #pragma unroll
    for (int i = 0; i < 4; i++) {
        int m = tid + i*256;
        v[i] = p[m] * mk[m];
        mx = fmaxf(mx, v[i]);
    }
    red[tid] = mx; __syncthreads();
    for (int s = 128; s > 0; s >>= 1) {
        if (tid < s) red[tid] = fmaxf(red[tid], red[tid + s]);
        __syncthreads();
    }
    mx = red[0]; __syncthreads();
    float sum = 0.f;
    #pragma unroll
    for (int i = 0; i < 4; i++) { v[i] = __expf(v[i] - mx); sum += v[i]; }
    red[tid] = sum; __syncthreads();
    for (int s = 128; s > 0; s >>= 1) {
        if (tid < s) red[tid] += red[tid + s];
        __syncthreads();
    }
    float total = red[0];
    #pragma unroll
    for (int i = 0; i < 4; i++) p[tid + i*256] = v[i];
    if (tid == 0) g_ib[row] = 1.f / total;
}

// ---------------------------------------------------------------------------
// GEMM 3 (batched TN): alphas[b,m,d] = inv_a[b,m]*mask2[b,m] *
//                                       sum_l g_ea[b,l,m] * s1[b,l,d]
// M=1024 (m), N=600 (d), K=1024 (l)
// ---------------------------------------------------------------------------
__global__ __launch_bounds__(256)
void k_gemm_alpha(const float* __restrict__ S1,
                  const float* __restrict__ mask2,
                  float* __restrict__ OUT) {
    int b = blockIdx.z;
    const float* A  = g_ea + (size_t)b*LL*LL;   // [l][m]
    const float* Bm = S1   + (size_t)b*LL*NI;   // [l][d]
    float*       C  = OUT  + (size_t)b*LL*NI;   // [m][d]
    __shared__ __align__(16) float As[16][64];
    __shared__ __align__(16) float Bs[16][64];
    int tid = threadIdx.x;
    int tx = tid & 15, ty = tid >> 4;
    int row0 = blockIdx.y * 64, col0 = blockIdx.x * 64;
    float acc[4][4] = {};
    for (int k0 = 0; k0 < LL; k0 += 16) {
        #pragma unroll
        for (int t = 0; t < 4; t++) {
            int idx = tid + t*256;
            int i = idx & 63, kk = idx >> 6;
            As[kk][i] = A[(size_t)(k0 + kk)*LL + row0 + i];
        }
        #pragma unroll
        for (int t = 0; t < 4; t++) {
            int idx = tid + t*256;
            int c = idx & 63, kk = idx >> 6;
            int gc = col0 + c;
            Bs[kk][c] = (gc < NI) ? Bm[(size_t)(k0 + kk)*NI + gc] : 0.f;
        }
        __syncthreads();
        #pragma unroll
        for (int kk = 0; kk < 16; kk++) {
            float4 a4 = *reinterpret_cast<const float4*>(&As[kk][ty*4]);
            float4 b4 = *reinterpret_cast<const float4*>(&Bs[kk][tx*4]);
            float a[4] = {a4.x, a4.y, a4.z, a4.w};
            float bb[4] = {b4.x, b4.y, b4.z, b4.w};
            #pragma unroll
            for (int i = 0; i < 4; i++)
                #pragma unroll
                for (int j = 0; j < 4; j++)
                    acc[i][j] = fmaf(a[i], bb[j], acc[i][j]);
        }
        __syncthreads();
    }
    #pragma unroll
    for (int i = 0; i < 4; i++) {
        int r = row0 + ty*4 + i;  // m
        float scale = g_ia[b*LL + r] * mask2[b*LL + r];
        #pragma unroll
        for (int j = 0; j < 4; j++) {
            int c = col0 + tx*4 + j;
            if (c < NI) C[(size_t)r*NI + c] = acc[i][j] * scale;
        }
    }
}

// ---------------------------------------------------------------------------
// GEMM 4 (batched NN): betas[b,l,d] = inv_b[b,l]*mask1[b,l] *
//                                      sum_m g_e[b,l,m] * s2[b,m,d]
// M=1024 (l), N=600 (d), K=1024 (m)
// ---------------------------------------------------------------------------
__global__ __launch_bounds__(256)
void k_gemm_beta(const float* __restrict__ S2,
                 const float* __restrict__ mask1,
                 float* __restrict__ OUT) {
    int b = blockIdx.z;
    const float* A  = g_e + (size_t)b*LL*LL;    // [l][m]
    const float* Bm = S2  + (size_t)b*LL*NI;    // [m][d]
    float*       C  = OUT + (size_t)b*LL*NI;    // [l][d]
    __shared__ __align__(16) float As[16][64];
    __shared__ __align__(16) float Bs[16][64];
    int tid = threadIdx.x;
    int tx = tid & 15, ty = tid >> 4;
    int row0 = blockIdx.y * 64, col0 = blockIdx.x * 64;
    float acc[4][4] = {};
    for (int k0 = 0; k0 < LL; k0 += 16) {
        #pragma unroll
        for (int t = 0; t < 4; t++) {
            int idx = tid + t*256;
            int r = idx >> 4, kk = idx & 15;
            As[kk][r] = A[(size_t)(row0 + r)*LL + k0 + kk];
        }
        #pragma unroll
        for (int t = 0; t < 4; t++) {
            int idx = tid + t*256;
            int c = idx & 63, kk = idx >> 6;
            int gc = col0 + c;
            Bs[kk][c] = (gc < NI) ? Bm[(size_t)(k0 + kk)*NI + gc] : 0.f;
        }
        __syncthreads();
        #pragma unroll
        for (int kk = 0; kk < 16; kk++) {
            float4 a4 = *reinterpret_cast<const float4*>(&As[kk][ty*4]);
            float4 b4 = *reinterpret_cast<const float4*>(&Bs[kk][tx*4]);
            float a[4] = {a4.x, a4.y, a4.z, a4.w};
            float bb[4] = {b4.x, b4.y, b4.z, b4.w};
            #pragma unroll
            for (int i = 0; i < 4; i++)
                #pragma unroll
                for (int j = 0; j < 4; j++)
                    acc[i][j] = fmaf(a[i], bb[j], acc[i][j]);
        }
        __syncthreads();
    }
    #pragma unroll
    for (int i = 0; i < 4; i++) {
        int r = row0 + ty*4 + i;  // l
        float scale = g_ib[b*LL + r] * mask1[b*LL + r];
        #pragma unroll
        for (int j = 0; j < 4; j++) {
            int c = col0 + tx*4 + j;
            if (c < NI) C[(size_t)r*NI + c] = acc[i][j] * scale;
        }
    }
}

// ---------------------------------------------------------------------------
extern "C" void kernel_launch(void* const* d_in, const int* in_sizes, int n_in,
                              void* d_out, int out_size) {
    const float* s1    = (const float*)d_in[0];
    const float* s2    = (const float*)d_in[1];
    const float* mask1 = (const float*)d_in[2];
    const float* mask2 = (const float*)d_in[3];
    const float* W1    = (const float*)d_in[4];
    const float* b1    = (const float*)d_in[5];
    const float* W2    = (const float*)d_in[6];
    const float* b2    = (const float*)d_in[7];
    float* out       = (float*)d_out;
    float* out_alpha = out;
    float* out_beta  = out + (size_t)NB*LL*NI;

    float *p_t, *p_h1, *p_h2;
    cudaGetSymbolAddress((void**)&p_t,  g_t);
    cudaGetSymbolAddress((void**)&p_h1, g_h1);
    cudaGetSymbolAddress((void**)&p_h2, g_h2);

    dim3 blk(256);

    // MLP for s1: t = relu(s1@W1+b1); h1 = relu(t@W2+b2)
    {
        dim3 g1((NH + 63) / 64, NR / 64);
        k_gemm_bias_relu<<<g1, blk>>>(s1,  W1, b1, p_t,  NR, NH, NI);
        k_gemm_bias_relu<<<g1, blk>>>(p_t, W2, b2, p_h1, NR, NH, NH);
        // MLP for s2
        k_gemm_bias_relu<<<g1, blk>>>(s2,  W1, b1, p_t,  NR, NH, NI);
        k_gemm_bias_relu<<<g1, blk>>>(p_t, W2, b2, p_h2, NR, NH, NH);
    }

    // e = h1 @ h2^T (batched)
    {
        dim3 ge(LL / 64, LL / 64, NB);
        k_gemm_e<<<ge, blk>>>();
    }

    // alpha softmax (reads g_e, writes g_ea + g_ia) — must precede in-place beta
    {
        dim3 gs(LL / 256, NB);
        k_softmax_cols<<<gs, blk>>>(mask1);
    }
    // beta softmax in-place on g_e (+ g_ib)
    k_softmax_rows<<<NR, blk>>>(mask2);

    // alphas and betas (normalization + mask folded into epilogues)
    {
        dim3 ga((NI + 63) / 64, LL / 64, NB);
        k_gemm_alpha<<<ga, blk>>>(s1, mask2, out_alpha);
        k_gemm_beta <<<ga, blk>>>(s2, mask1, out_beta);
    }
}

// round 7
// speedup vs baseline: 1.5541x; 1.5541x over previous
#include <cuda_runtime.h>
#include <math.h>

#define NB 32
#define LL 1024
#define NI 600
#define NH 200
#define NR (NB*LL)

// ---------------- scratch (device globals; no runtime allocation) ----------
__device__ float g_t [NR*NH];                 // MLP layer1 temp
__device__ float g_h1[NR*NH];                 // mlp(s1)
__device__ float g_h2[NR*NH];                 // mlp(s2)
__device__ float g_e [(size_t)NB*LL*LL];      // e, then in-place exp for beta
__device__ float g_ea[(size_t)NB*LL*LL];      // un-normalized exp for alpha
__device__ float g_ia[NR];                    // 1/sum per (b,m) for alpha
__device__ float g_ib[NR];                    // 1/sum per (b,l) for beta

// ---------------------------------------------------------------------------
// Unified 128x128x8 SGEMM, 256 threads, 8x8 micro-tile, register prefetch.
//   EPI: 0 = plain store, 1 = relu(acc + P1[c]), 2 = acc * P1[b*LL+r]*P2[b*LL+r]
//   ATR: A global is [M][K] (k-contiguous, transpose on smem store)
//        else A is [K][M] (m-contiguous, direct smem store)
//   BTR: B global is [N][K] (transpose on store) else [K][N] direct
//   NG : N needs bounds guards (N not multiple of 128)
// Requirements: M % 128 == 0, K % 8 == 0 (true for all shapes here).
// ---------------------------------------------------------------------------
template<int EPI, bool ATR, bool BTR, bool NG>
__global__ __launch_bounds__(256, 2)
void gemm128(const float* __restrict__ Ag, const float* __restrict__ Bg,
             const float* __restrict__ P1, const float* __restrict__ P2,
             float* __restrict__ Cg,
             int N, int K, int lda, int ldb, int ldc,
             size_t sA, size_t sB, size_t sC)
{
    const int b = blockIdx.z;
    const float* A = Ag + (size_t)b * sA;
    const float* B = Bg + (size_t)b * sB;
    float*       C = Cg + (size_t)b * sC;

    __shared__ __align__(16) float As[8][132];
    __shared__ __align__(16) float Bs[8][132];

    const int tid  = threadIdx.x;
    const int tx   = tid & 15;           // 0..15 col group
    const int ty   = tid >> 4;           // 0..15 row group
    const int row0 = blockIdx.y * 128;
    const int col0 = blockIdx.x * 128;

    // load-index precompute
    const int t2r  = tid >> 1;           // 0..127 (transpose loads)
    const int t2k  = (tid & 1) * 4;      // 0 or 4
    const int t32k = tid >> 5;           // 0..7   (direct loads)
    const int t32c = (tid & 31) * 4;     // 0..124

    float acc[8][8] = {};
    float4 ra, rb;

    auto loadA = [&](int k0) {
        if (ATR) {
            ra = *reinterpret_cast<const float4*>(&A[(size_t)(row0 + t2r) * lda + k0 + t2k]);
        } else {
            ra = *reinterpret_cast<const float4*>(&A[(size_t)(k0 + t32k) * lda + row0 + t32c]);
        }
    };
    auto loadB = [&](int k0) {
        if (BTR) {
            rb = *reinterpret_cast<const float4*>(&B[(size_t)(col0 + t2r) * ldb + k0 + t2k]);
        } else {
            int gc = col0 + t32c;
            const float* p = &B[(size_t)(k0 + t32k) * ldb + gc];
            if (!NG || gc + 3 < N) {
                rb = *reinterpret_cast<const float4*>(p);
            } else {
                rb.x = (gc + 0 < N) ? p[0] : 0.f;
                rb.y = (gc + 1 < N) ? p[1] : 0.f;
                rb.z = (gc + 2 < N) ? p[2] : 0.f;
                rb.w = (gc + 3 < N) ? p[3] : 0.f;
            }
        }
    };
    auto storeA = [&]() {
        if (ATR) {
            As[t2k + 0][t2r] = ra.x; As[t2k + 1][t2r] = ra.y;
            As[t2k + 2][t2r] = ra.z; As[t2k + 3][t2r] = ra.w;
        } else {
            *reinterpret_cast<float4*>(&As[t32k][t32c]) = ra;
        }
    };
    auto storeB = [&]() {
        if (BTR) {
            Bs[t2k + 0][t2r] = rb.x; Bs[t2k + 1][t2r] = rb.y;
            Bs[t2k + 2][t2r] = rb.z; Bs[t2k + 3][t2r] = rb.w;
        } else {
            *reinterpret_cast<float4*>(&Bs[t32k][t32c]) = rb;
        }
    };

    loadA(0); loadB(0);
    for (int k0 = 0; k0 < K; k0 += 8) {
        storeA(); storeB();
        __syncthreads();
        if (k0 + 8 < K) { loadA(k0 + 8); loadB(k0 + 8); }   // prefetch next tile
        #pragma unroll
        for (int kk = 0; kk < 8; kk++) {
            float4 a0 = *reinterpret_cast<const float4*>(&As[kk][ty * 4]);
            float4 a1 = *reinterpret_cast<const float4*>(&As[kk][64 + ty * 4]);
            float4 b0 = *reinterpret_cast<const float4*>(&Bs[kk][tx * 4]);
            float4 b1 = *reinterpret_cast<const float4*>(&Bs[kk][64 + tx * 4]);
            float av[8] = {a0.x, a0.y, a0.z, a0.w, a1.x, a1.y, a1.z, a1.w};
            float bv[8] = {b0.x, b0.y, b0.z, b0.w, b1.x, b1.y, b1.z, b1.w};
            #pragma unroll
            for (int i = 0; i < 8; i++)
                #pragma unroll
                for (int j = 0; j < 8; j++)
                    acc[i][j] = fmaf(av[i], bv[j], acc[i][j]);
        }
        __syncthreads();
    }

    #pragma unroll
    for (int ri = 0; ri < 2; ri++) {
        #pragma unroll
        for (int i = 0; i < 4; i++) {
            int r = row0 + ri * 64 + ty * 4 + i;
            float scale = 1.f;
            if (EPI == 2) scale = P1[b * LL + r] * P2[b * LL + r];
            #pragma unroll
            for (int ci = 0; ci < 2; ci++) {
                #pragma unroll
                for (int j = 0; j < 4; j++) {
                    int c = col0 + ci * 64 + tx * 4 + j;
                    if (NG && c >= N) continue;
                    float v = acc[ri * 4 + i][ci * 4 + j];
                    if (EPI == 1) v = fmaxf(v + P1[c], 0.f);
                    if (EPI == 2) v *= scale;
                    C[(size_t)r * ldc + c] = v;
                }
            }
        }
    }
}

// ---------------------------------------------------------------------------
// Alpha softmax (over l, per column m): UN-normalized exp into g_ea, 1/sum
// into g_ia.  logit[l,m] = e[l,m] * mask1[b,l]
// ---------------------------------------------------------------------------
__global__ __launch_bounds__(256)
void k_softmax_cols(const float* __restrict__ mask1) {
    int b = blockIdx.y;
    int m = blockIdx.x * 256 + threadIdx.x;
    const float* pe = g_e  + (size_t)b*LL*LL + m;
    float*       po = g_ea + (size_t)b*LL*LL + m;
    __shared__ float smk[LL];
    for (int l = threadIdx.x; l < LL; l += 256) smk[l] = mask1[b*LL + l];
    __syncthreads();
    float mx = -3.4e38f;
    for (int l = 0; l < LL; l++) {
        float v = pe[(size_t)l*LL] * smk[l];
        mx = fmaxf(mx, v);
    }
    float s = 0.f;
    for (int l = 0; l < LL; l++) {
        float t = __expf(pe[(size_t)l*LL] * smk[l] - mx);
        po[(size_t)l*LL] = t;
        s += t;
    }
    g_ia[b*LL + m] = 1.f / s;
}

// ---------------------------------------------------------------------------
// Beta softmax (over m, per row l): IN-PLACE on g_e, 1/sum into g_ib.
// ---------------------------------------------------------------------------
__global__ __launch_bounds__(256)
void k_softmax_rows(const float* __restrict__ mask2) {
    int row = blockIdx.x;        // b*LL + l
    int b = row >> 10;
    float* p = g_e + (size_t)row*LL;
    const float* mk = mask2 + b*LL;
    int tid = threadIdx.x;
    __shared__ float red[256];
    float v[4];
    float mx = -3.4e38f;
    #pragma unroll
    for (int i = 0; i < 4; i++) {
        int m = tid + i*256;
        v[i] = p[m] * mk[m];
        mx = fmaxf(mx, v[i]);
    }
    red[tid] = mx; __syncthreads();
    for (int s = 128; s > 0; s >>= 1) {
        if (tid < s) red[tid] = fmaxf(red[tid], red[tid + s]);
        __syncthreads();
    }
    mx = red[0]; __syncthreads();
    float sum = 0.f;
    #pragma unroll
    for (int i = 0; i < 4; i++) { v[i] = __expf(v[i] - mx); sum += v[i]; }
    red[tid] = sum; __syncthreads();
    for (int s = 128; s > 0; s >>= 1) {
        if (tid < s) red[tid] += red[tid + s];
        __syncthreads();
    }
    float total = red[0];
    #pragma unroll
    for (int i = 0; i < 4; i++) p[tid + i*256] = v[i];
    if (tid == 0) g_ib[row] = 1.f / total;
}

// ---------------------------------------------------------------------------
extern "C" void kernel_launch(void* const* d_in, const int* in_sizes, int n_in,
                              void* d_out, int out_size) {
    const float* s1    = (const float*)d_in[0];
    const float* s2    = (const float*)d_in[1];
    const float* mask1 = (const float*)d_in[2];
    const float* mask2 = (const float*)d_in[3];
    const float* W1    = (const float*)d_in[4];
    const float* b1    = (const float*)d_in[5];
    const float* W2    = (const float*)d_in[6];
    const float* b2    = (const float*)d_in[7];
    float* out       = (float*)d_out;
    float* out_alpha = out;
    float* out_beta  = out + (size_t)NB*LL*NI;

    float *p_t, *p_h1, *p_h2, *p_e, *p_ea, *p_ia, *p_ib;
    cudaGetSymbolAddress((void**)&p_t,  g_t);
    cudaGetSymbolAddress((void**)&p_h1, g_h1);
    cudaGetSymbolAddress((void**)&p_h2, g_h2);
    cudaGetSymbolAddress((void**)&p_e,  g_e);
    cudaGetSymbolAddress((void**)&p_ea, g_ea);
    cudaGetSymbolAddress((void**)&p_ia, g_ia);
    cudaGetSymbolAddress((void**)&p_ib, g_ib);

    dim3 blk(256);

    // ---- MLP: h = relu(relu(x@W1+b1)@W2+b2) for both streams -------------
    // M=32768 (mult of 128), N=200 (guarded), K=600/200 (mult of 8)
    {
        dim3 g1((NH + 127) / 128, NR / 128, 1);   // (2, 256)
        gemm128<1,true,false,true><<<g1, blk>>>(s1,  W1, b1, nullptr, p_t,
                                                NH, NI, NI, NH, NH, 0, 0, 0);
        gemm128<1,true,false,true><<<g1, blk>>>(p_t, W2, b2, nullptr, p_h1,
                                                NH, NH, NH, NH, NH, 0, 0, 0);
        gemm128<1,true,false,true><<<g1, blk>>>(s2,  W1, b1, nullptr, p_t,
                                                NH, NI, NI, NH, NH, 0, 0, 0);
        gemm128<1,true,false,true><<<g1, blk>>>(p_t, W2, b2, nullptr, p_h2,
                                                NH, NH, NH, NH, NH, 0, 0, 0);
    }

    // ---- e[b,l,m] = h1 @ h2^T : NT, M=N=1024, K=200 -----------------------
    {
        dim3 ge(LL / 128, LL / 128, NB);          // (8, 8, 32)
        gemm128<0,true,true,false><<<ge, blk>>>(p_h1, p_h2, nullptr, nullptr, p_e,
                                                LL, NH, NH, NH, LL,
                                                (size_t)LL*NH, (size_t)LL*NH, (size_t)LL*LL);
    }

    // ---- softmaxes (alpha first: beta overwrites g_e in place) ------------
    {
        dim3 gs(LL / 256, NB);
        k_softmax_cols<<<gs, blk>>>(mask1);
    }
    k_softmax_rows<<<NR, blk>>>(mask2);

    // ---- alphas (TN) and betas (NN): M=1024, N=600, K=1024 ----------------
    {
        dim3 ga((NI + 127) / 128, LL / 128, NB);  // (5, 8, 32)
        // alphas[b,m,d] = (inv_a*mask2)[b,m] * sum_l ea[b,l,m] * s1[b,l,d]
        gemm128<2,false,false,true><<<ga, blk>>>(p_ea, s1, p_ia, mask2, out_alpha,
                                                 NI, LL, LL, NI, NI,
                                                 (size_t)LL*LL, (size_t)LL*NI, (size_t)LL*NI);
        // betas[b,l,d] = (inv_b*mask1)[b,l] * sum_m e[b,l,m] * s2[b,m,d]
        gemm128<2,true,false,true><<<ga, blk>>>(p_e, s2, p_ib, mask1, out_beta,
                                                NI, LL, LL, NI, NI,
                                                (size_t)LL*LL, (size_t)LL*NI, (size_t)LL*NI);
    }
}

// round 8
// speedup vs baseline: 1.5550x; 1.0006x over previous
#include <cuda_runtime.h>
#include <math.h>

#define NB 32
#define LL 1024
#define NI 600
#define NH 200
#define NR (NB*LL)

// ---------------- scratch (device globals; no runtime allocation) ----------
__device__ float g_t [NR*NH];                 // MLP layer1 temp
__device__ float g_h1[NR*NH];                 // mlp(s1)
__device__ float g_h2[NR*NH];                 // mlp(s2)
__device__ float g_e [(size_t)NB*LL*LL];      // e, then in-place exp for beta
__device__ float g_ea[(size_t)NB*LL*LL];      // un-normalized exp for alpha
__device__ float g_ia[NR];                    // 1/sum per (b,m) for alpha
__device__ float g_ib[NR];                    // 1/sum per (b,l) for beta

// ---------------------------------------------------------------------------
// Unified 128x128x8 SGEMM, 256 threads, 8x8 micro-tile, register prefetch.
//   EPI: 0 = plain store, 1 = relu(acc + P1[c]), 2 = acc * P1[b*LL+r]*P2[b*LL+r]
//   ATR: A global is [M][K] (k-contiguous, transpose on smem store)
//        else A is [K][M] (m-contiguous, direct smem store)
//   BTR: B global is [N][K] (transpose on store) else [K][N] direct
//   NG : N needs bounds guards (N not multiple of 128)
// Requirements: M % 128 == 0, K % 8 == 0 (true for all shapes here).
// ---------------------------------------------------------------------------
template<int EPI, bool ATR, bool BTR, bool NG>
__global__ __launch_bounds__(256, 2)
void gemm128(const float* __restrict__ Ag, const float* __restrict__ Bg,
             const float* __restrict__ P1, const float* __restrict__ P2,
             float* __restrict__ Cg,
             int N, int K, int lda, int ldb, int ldc,
             size_t sA, size_t sB, size_t sC)
{
    const int b = blockIdx.z;
    const float* A = Ag + (size_t)b * sA;
    const float* B = Bg + (size_t)b * sB;
    float*       C = Cg + (size_t)b * sC;

    __shared__ __align__(16) float As[8][132];
    __shared__ __align__(16) float Bs[8][132];

    const int tid  = threadIdx.x;
    const int tx   = tid & 15;           // 0..15 col group
    const int ty   = tid >> 4;           // 0..15 row group
    const int row0 = blockIdx.y * 128;
    const int col0 = blockIdx.x * 128;

    // load-index precompute
    const int t2r  = tid >> 1;           // 0..127 (transpose loads)
    const int t2k  = (tid & 1) * 4;      // 0 or 4
    const int t32k = tid >> 5;           // 0..7   (direct loads)
    const int t32c = (tid & 31) * 4;     // 0..124

    float acc[8][8] = {};
    float4 ra, rb;

    auto loadA = [&](int k0) {
        if (ATR) {
            ra = *reinterpret_cast<const float4*>(&A[(size_t)(row0 + t2r) * lda + k0 + t2k]);
        } else {
            ra = *reinterpret_cast<const float4*>(&A[(size_t)(k0 + t32k) * lda + row0 + t32c]);
        }
    };
    auto loadB = [&](int k0) {
        if (BTR) {
            rb = *reinterpret_cast<const float4*>(&B[(size_t)(col0 + t2r) * ldb + k0 + t2k]);
        } else {
            int gc = col0 + t32c;
            const float* p = &B[(size_t)(k0 + t32k) * ldb + gc];
            if (!NG || gc + 3 < N) {
                rb = *reinterpret_cast<const float4*>(p);
            } else {
                rb.x = (gc + 0 < N) ? p[0] : 0.f;
                rb.y = (gc + 1 < N) ? p[1] : 0.f;
                rb.z = (gc + 2 < N) ? p[2] : 0.f;
                rb.w = (gc + 3 < N) ? p[3] : 0.f;
            }
        }
    };
    auto storeA = [&]() {
        if (ATR) {
            As[t2k + 0][t2r] = ra.x; As[t2k + 1][t2r] = ra.y;
            As[t2k + 2][t2r] = ra.z; As[t2k + 3][t2r] = ra.w;
        } else {
            *reinterpret_cast<float4*>(&As[t32k][t32c]) = ra;
        }
    };
    auto storeB = [&]() {
        if (BTR) {
            Bs[t2k + 0][t2r] = rb.x; Bs[t2k + 1][t2r] = rb.y;
            Bs[t2k + 2][t2r] = rb.z; Bs[t2k + 3][t2r] = rb.w;
        } else {
            *reinterpret_cast<float4*>(&Bs[t32k][t32c]) = rb;
        }
    };

    loadA(0); loadB(0);
    for (int k0 = 0; k0 < K; k0 += 8) {
        storeA(); storeB();
        __syncthreads();
        if (k0 + 8 < K) { loadA(k0 + 8); loadB(k0 + 8); }   // prefetch next tile
        #pragma unroll
        for (int kk = 0; kk < 8; kk++) {
            float4 a0 = *reinterpret_cast<const float4*>(&As[kk][ty * 4]);
            float4 a1 = *reinterpret_cast<const float4*>(&As[kk][64 + ty * 4]);
            float4 b0 = *reinterpret_cast<const float4*>(&Bs[kk][tx * 4]);
            float4 b1 = *reinterpret_cast<const float4*>(&Bs[kk][64 + tx * 4]);
            float av[8] = {a0.x, a0.y, a0.z, a0.w, a1.x, a1.y, a1.z, a1.w};
            float bv[8] = {b0.x, b0.y, b0.z, b0.w, b1.x, b1.y, b1.z, b1.w};
            #pragma unroll
            for (int i = 0; i < 8; i++)
                #pragma unroll
                for (int j = 0; j < 8; j++)
                    acc[i][j] = fmaf(av[i], bv[j], acc[i][j]);
        }
        __syncthreads();
    }

    #pragma unroll
    for (int ri = 0; ri < 2; ri++) {
        #pragma unroll
        for (int i = 0; i < 4; i++) {
            int r = row0 + ri * 64 + ty * 4 + i;
            float scale = 1.f;
            if (EPI == 2) scale = P1[b * LL + r] * P2[b * LL + r];
            #pragma unroll
            for (int ci = 0; ci < 2; ci++) {
                #pragma unroll
                for (int j = 0; j < 4; j++) {
                    int c = col0 + ci * 64 + tx * 4 + j;
                    if (NG && c >= N) continue;
                    float v = acc[ri * 4 + i][ci * 4 + j];
                    if (EPI == 1) v = fmaxf(v + P1[c], 0.f);
                    if (EPI == 2) v *= scale;
                    C[(size_t)r * ldc + c] = v;
                }
            }
        }
    }
}

// ---------------------------------------------------------------------------
// Alpha softmax (over l, per column m): UN-normalized exp into g_ea, 1/sum
// into g_ia.  logit[l,m] = e[l,m] * mask1[b,l]
// ---------------------------------------------------------------------------
__global__ __launch_bounds__(256)
void k_softmax_cols(const float* __restrict__ mask1) {
    int b = blockIdx.y;
    int m = blockIdx.x * 256 + threadIdx.x;
    const float* pe = g_e  + (size_t)b*LL*LL + m;
    float*       po = g_ea + (size_t)b*LL*LL + m;
    __shared__ float smk[LL];
    for (int l = threadIdx.x; l < LL; l += 256) smk[l] = mask1[b*LL + l];
    __syncthreads();
    float mx = -3.4e38f;
    for (int l = 0; l < LL; l++) {
        float v = pe[(size_t)l*LL] * smk[l];
        mx = fmaxf(mx, v);
    }
    float s = 0.f;
    for (int l = 0; l < LL; l++) {
        float t = __expf(pe[(size_t)l*LL] * smk[l] - mx);
        po[(size_t)l*LL] = t;
        s += t;
    }
    g_ia[b*LL + m] = 1.f / s;
}

// ---------------------------------------------------------------------------
// Beta softmax (over m, per row l): IN-PLACE on g_e, 1/sum into g_ib.
// ---------------------------------------------------------------------------
__global__ __launch_bounds__(256)
void k_softmax_rows(const float* __restrict__ mask2) {
    int row = blockIdx.x;        // b*LL + l
    int b = row >> 10;
    float* p = g_e + (size_t)row*LL;
    const float* mk = mask2 + b*LL;
    int tid = threadIdx.x;
    __shared__ float red[256];
    float v[4];
    float mx = -3.4e38f;
    #pragma unroll
    for (int i = 0; i < 4; i++) {
        int m = tid + i*256;
        v[i] = p[m] * mk[m];
        mx = fmaxf(mx, v[i]);
    }
    red[tid] = mx; __syncthreads();
    for (int s = 128; s > 0; s >>= 1) {
        if (tid < s) red[tid] = fmaxf(red[tid], red[tid + s]);
        __syncthreads();
    }
    mx = red[0]; __syncthreads();
    float sum = 0.f;
    #pragma unroll
    for (int i = 0; i < 4; i++) { v[i] = __expf(v[i] - mx); sum += v[i]; }
    red[tid] = sum; __syncthreads();
    for (int s = 128; s > 0; s >>= 1) {
        if (tid < s) red[tid] += red[tid + s];
        __syncthreads();
    }
    float total = red[0];
    #pragma unroll
    for (int i = 0; i < 4; i++) p[tid + i*256] = v[i];
    if (tid == 0) g_ib[row] = 1.f / total;
}

// ---------------------------------------------------------------------------
extern "C" void kernel_launch(void* const* d_in, const int* in_sizes, int n_in,
                              void* d_out, int out_size) {
    const float* s1    = (const float*)d_in[0];
    const float* s2    = (const float*)d_in[1];
    const float* mask1 = (const float*)d_in[2];
    const float* mask2 = (const float*)d_in[3];
    const float* W1    = (const float*)d_in[4];
    const float* b1    = (const float*)d_in[5];
    const float* W2    = (const float*)d_in[6];
    const float* b2    = (const float*)d_in[7];
    float* out       = (float*)d_out;
    float* out_alpha = out;
    float* out_beta  = out + (size_t)NB*LL*NI;

    float *p_t, *p_h1, *p_h2, *p_e, *p_ea, *p_ia, *p_ib;
    cudaGetSymbolAddress((void**)&p_t,  g_t);
    cudaGetSymbolAddress((void**)&p_h1, g_h1);
    cudaGetSymbolAddress((void**)&p_h2, g_h2);
    cudaGetSymbolAddress((void**)&p_e,  g_e);
    cudaGetSymbolAddress((void**)&p_ea, g_ea);
    cudaGetSymbolAddress((void**)&p_ia, g_ia);
    cudaGetSymbolAddress((void**)&p_ib, g_ib);

    dim3 blk(256);

    // ---- MLP: h = relu(relu(x@W1+b1)@W2+b2) for both streams -------------
    // M=32768 (mult of 128), N=200 (guarded), K=600/200 (mult of 8)
    {
        dim3 g1((NH + 127) / 128, NR / 128, 1);   // (2, 256)
        gemm128<1,true,false,true><<<g1, blk>>>(s1,  W1, b1, nullptr, p_t,
                                                NH, NI, NI, NH, NH, 0, 0, 0);
        gemm128<1,true,false,true><<<g1, blk>>>(p_t, W2, b2, nullptr, p_h1,
                                                NH, NH, NH, NH, NH, 0, 0, 0);
        gemm128<1,true,false,true><<<g1, blk>>>(s2,  W1, b1, nullptr, p_t,
                                                NH, NI, NI, NH, NH, 0, 0, 0);
        gemm128<1,true,false,true><<<g1, blk>>>(p_t, W2, b2, nullptr, p_h2,
                                                NH, NH, NH, NH, NH, 0, 0, 0);
    }

    // ---- e[b,l,m] = h1 @ h2^T : NT, M=N=1024, K=200 -----------------------
    {
        dim3 ge(LL / 128, LL / 128, NB);          // (8, 8, 32)
        gemm128<0,true,true,false><<<ge, blk>>>(p_h1, p_h2, nullptr, nullptr, p_e,
                                                LL, NH, NH, NH, LL,
                                                (size_t)LL*NH, (size_t)LL*NH, (size_t)LL*LL);
    }

    // ---- softmaxes (alpha first: beta overwrites g_e in place) ------------
    {
        dim3 gs(LL / 256, NB);
        k_softmax_cols<<<gs, blk>>>(mask1);
    }
    k_softmax_rows<<<NR, blk>>>(mask2);

    // ---- alphas (TN) and betas (NN): M=1024, N=600, K=1024 ----------------
    {
        dim3 ga((NI + 127) / 128, LL / 128, NB);  // (5, 8, 32)
        // alphas[b,m,d] = (inv_a*mask2)[b,m] * sum_l ea[b,l,m] * s1[b,l,d]
        gemm128<2,false,false,true><<<ga, blk>>>(p_ea, s1, p_ia, mask2, out_alpha,
                                                 NI, LL, LL, NI, NI,
                                                 (size_t)LL*LL, (size_t)LL*NI, (size_t)LL*NI);
        // betas[b,l,d] = (inv_b*mask1)[b,l] * sum_m e[b,l,m] * s2[b,m,d]
        gemm128<2,true,false,true><<<ga, blk>>>(p_e, s2, p_ib, mask1, out_beta,
                                                NI, LL, LL, NI, NI,
                                                (size_t)LL*LL, (size_t)LL*NI, (size_t)LL*NI);
    }
}